// round 13
// baseline (speedup 1.0000x reference)
#include <cuda_runtime.h>
#include <cuda_bf16.h>
#include <math.h>

#define NE      65536
#define NATOMS  2048
#define NRAD    24
#define NCOMP   5        // 1 two-body + 4 zetas
#define KTOT    69       // 4 + 10 + 20 + 35
#define NPAIR   (NRAD*KTOT)   // 1656
#define FEAT    216      // 24 * (1 + 2*4)
#define EMBD    16
#define NELEM   94
#define H1N     256
#define H2N     128
#define TS      16       // seg tile (edges per step)
#define TROW    189      // 120 radial + 69 angular channels per edge
#define TSTRIDE 18       // smem stride per channel row (even -> 8B aligned pairs)
#define TILEW   (TROW*TSTRIDE)  // 3402

typedef unsigned long long u64;

// ---------------- device scratch (no allocations allowed) ----------------
__device__ float g_radial[120 * NE];           // [chan][E]  (transposed, coalesced)
__device__ float g_gv[KTOT * NE];              // [k][E]
__device__ float g_feat[NATOMS * FEAT];        // [nat,216]
__device__ float g_B[(size_t)NELEM * FEAT * H1N]; // [94,216,256] folded Wa1
__device__ int   g_segstart[NATOMS + 1];
__device__ int   g_cnt[NELEM];
__device__ int   g_off[NELEM];
__device__ int   g_order[NATOMS];
__device__ float g_energy[NATOMS];

// k-chunk table: 32 lanes cover 69 angular channels, chunks never cross a zone
// boundary (zones: k in [0,4) [4,14) [14,34) [34,69)).
__constant__ int c_klo[32] = {0,2,4,6,8,10,12,14,17,20,23,26,29,32,
                              34,36,38,40,42,44,46,48,50,52,54,56,58,60,62,64,66,68};
__constant__ int c_nk[32]  = {2,2,2,2,2,2,2,3,3,3,3,3,3,2,
                              2,2,2,2,2,2,2,2,2,2,2,2,2,2,2,2,2,1};

// ---------------- packed f32x2 helpers ----------------
__device__ __forceinline__ u64 pk2(float lo, float hi) {
    u64 r; asm("mov.b64 %0,{%1,%2};" : "=l"(r) : "f"(lo), "f"(hi)); return r;
}
__device__ __forceinline__ void upk2(u64 v, float& lo, float& hi) {
    asm("mov.b64 {%0,%1},%2;" : "=f"(lo), "=f"(hi) : "l"(v));
}
__device__ __forceinline__ u64 ffma2(u64 a, u64 b, u64 c) {
    u64 d; asm("fma.rn.f32x2 %0,%1,%2,%3;" : "=l"(d) : "l"(a), "l"(b), "l"(c)); return d;
}

__device__ __forceinline__ float silu_fast(float x) {
    return __fdividef(x, 1.f + __expf(-x));
}
__device__ __forceinline__ float silu_acc(float x) {
    return x / (1.f + expf(-x));
}

// ---------------- kernel: segment start offsets (kills per-CTA binary search) ----------------
__global__ __launch_bounds__(256) void segstart_kernel(const int* __restrict__ seg)
{
    int e = blockIdx.x * 256 + threadIdx.x;
    int cur = seg[e];
    int prev = (e == 0) ? -1 : seg[e - 1];
    for (int a = prev + 1; a <= cur; a++) g_segstart[a] = e;
    if (e == NE - 1)
        for (int a = cur + 1; a <= NATOMS; a++) g_segstart[a] = NE;
}

// ---------------- kernel: per-edge radial MLP + angular factors ----------------
// 2 edges per thread: every shared-memory weight load is reused for both edges.
__global__ __launch_bounds__(128) void edge_kernel(
    const float* __restrict__ rij,
    const float* __restrict__ Wr1, const float* __restrict__ br1,
    const float* __restrict__ Wr2, const float* __restrict__ br2)
{
    __shared__ __align__(16) float sW1[24 * 64];
    __shared__ __align__(16) float sW2[64 * 120];
    __shared__ __align__(16) float sb1[64];
    __shared__ __align__(16) float sb2[120];

    int tid = threadIdx.x;
    for (int i = tid; i < 24 * 64; i += 128)  sW1[i] = Wr1[i];
    for (int i = tid; i < 64 * 120; i += 128) sW2[i] = Wr2[i];
    if (tid < 64)  sb1[tid] = br1[tid];
    if (tid < 120) sb2[tid] = br2[tid];
    __syncthreads();

    int e0 = blockIdx.x * 256 + tid;
    int e1 = e0 + 128;

    float ux0, uy0, uz0, ux1, uy1, uz1;
    float basis0[24], basis1[24];
    {
        float x = rij[e0*3+0], y = rij[e0*3+1], z = rij[e0*3+2];
        float r = sqrtf(x*x + y*y + z*z);
        float inv = 1.f / r;
        ux0 = x*inv + 1e-12f; uy0 = y*inv + 1e-12f; uz0 = z*inv + 1e-12f;
        float fc = 0.5f * (__cosf(3.14159265358979323846f * fminf(r, 6.f) * (1.f/6.f)) + 1.f);
#pragma unroll
        for (int k = 0; k < 24; k++) {
            float d = r - (6.f/23.f)*(float)k;
            basis0[k] = __expf(-d*d*8.f) * fc;
        }
    }
    {
        float x = rij[e1*3+0], y = rij[e1*3+1], z = rij[e1*3+2];
        float r = sqrtf(x*x + y*y + z*z);
        float inv = 1.f / r;
        ux1 = x*inv + 1e-12f; uy1 = y*inv + 1e-12f; uz1 = z*inv + 1e-12f;
        float fc = 0.5f * (__cosf(3.14159265358979323846f * fminf(r, 6.f) * (1.f/6.f)) + 1.f);
#pragma unroll
        for (int k = 0; k < 24; k++) {
            float d = r - (6.f/23.f)*(float)k;
            basis1[k] = __expf(-d*d*8.f) * fc;
        }
    }

    // ---- layer 1: 24 -> 64, 2 chunks of 32 outputs, weights shared across edges ----
    float h0[64], h1[64];
#pragma unroll
    for (int c = 0; c < 2; c++) {
        u64 a0[16], a1[16];
        {
            const ulonglong2* bp = (const ulonglong2*)(sb1 + c * 32);
#pragma unroll
            for (int t = 0; t < 8; t++) {
                ulonglong2 b = bp[t];
                a0[2*t] = b.x; a0[2*t+1] = b.y;
                a1[2*t] = b.x; a1[2*t+1] = b.y;
            }
        }
#pragma unroll
        for (int k = 0; k < 24; k++) {
            u64 p0 = pk2(basis0[k], basis0[k]);
            u64 p1 = pk2(basis1[k], basis1[k]);
            const ulonglong2* w = (const ulonglong2*)(sW1 + k * 64 + c * 32);
#pragma unroll
            for (int t = 0; t < 8; t++) {
                ulonglong2 ww = w[t];
                a0[2*t]   = ffma2(p0, ww.x, a0[2*t]);
                a0[2*t+1] = ffma2(p0, ww.y, a0[2*t+1]);
                a1[2*t]   = ffma2(p1, ww.x, a1[2*t]);
                a1[2*t+1] = ffma2(p1, ww.y, a1[2*t+1]);
            }
        }
#pragma unroll
        for (int t = 0; t < 16; t++) {
            float x, y;
            upk2(a0[t], x, y);
            h0[c*32 + 2*t] = silu_fast(x); h0[c*32 + 2*t + 1] = silu_fast(y);
            upk2(a1[t], x, y);
            h1[c*32 + 2*t] = silu_fast(x); h1[c*32 + 2*t + 1] = silu_fast(y);
        }
    }

    // ---- layer 2: 64 -> 120, 6 chunks of 20 outputs, weights shared ----
#pragma unroll 1
    for (int c = 0; c < 6; c++) {
        u64 a0[10], a1[10];
        {
            const ulonglong2* bp = (const ulonglong2*)(sb2 + c * 20);
#pragma unroll
            for (int t = 0; t < 5; t++) {
                ulonglong2 b = bp[t];
                a0[2*t] = b.x; a0[2*t+1] = b.y;
                a1[2*t] = b.x; a1[2*t+1] = b.y;
            }
        }
#pragma unroll 16
        for (int j = 0; j < 64; j++) {
            u64 p0 = pk2(h0[j], h0[j]);
            u64 p1 = pk2(h1[j], h1[j]);
            const ulonglong2* w = (const ulonglong2*)(sW2 + j * 120 + c * 20);
#pragma unroll
            for (int t = 0; t < 5; t++) {
                ulonglong2 ww = w[t];
                a0[2*t]   = ffma2(p0, ww.x, a0[2*t]);
                a0[2*t+1] = ffma2(p0, ww.y, a0[2*t+1]);
                a1[2*t]   = ffma2(p1, ww.x, a1[2*t]);
                a1[2*t+1] = ffma2(p1, ww.y, a1[2*t+1]);
            }
        }
#pragma unroll
        for (int t = 0; t < 10; t++) {
            float x, y;
            int o = c * 20 + 2 * t;
            upk2(a0[t], x, y);
            g_radial[(size_t)o * NE + e0]       = silu_fast(x);
            g_radial[(size_t)(o + 1) * NE + e0] = silu_fast(y);
            upk2(a1[t], x, y);
            g_radial[(size_t)o * NE + e1]       = silu_fast(x);
            g_radial[(size_t)(o + 1) * NE + e1] = silu_fast(y);
        }
    }

    // ---- angular factors (both edges), compile-time enumeration ----
    const float FACT[5] = {1.f, 1.f, 2.f, 6.f, 24.f};
#pragma unroll
    for (int pass = 0; pass < 2; pass++) {
        float ux = pass ? ux1 : ux0, uy = pass ? uy1 : uy0, uz = pass ? uz1 : uz0;
        int e = pass ? e1 : e0;
        float px[5], py[5], pz[5];
        px[0] = 1.f; py[0] = 1.f; pz[0] = 1.f;
#pragma unroll
        for (int n = 1; n < 5; n++) { px[n] = px[n-1]*ux; py[n] = py[n-1]*uy; pz[n] = pz[n-1]*uz; }
        int k = 0;
#pragma unroll
        for (int z5 = 1; z5 <= 4; z5++) {
#pragma unroll
            for (int n = 0; n <= z5; n++) {
#pragma unroll
                for (int a = 0; a <= n; a++) {
#pragma unroll
                    for (int b = 0; b <= n - a; b++) {
                        int cc = n - a - b;
                        float fn = FACT[z5] / (FACT[z5 - n] * FACT[a] * FACT[b] * FACT[cc]);
                        g_gv[(size_t)k * NE + e] = fn * px[a] * py[b] * pz[cc];
                        k++;
                    }
                }
            }
        }
    }
}

// ---------------- seg tile loader: cp.async 8B with zero-fill tails ----------------
// s0 is guaranteed even -> all 8B sources are 8B-aligned.
__device__ __forceinline__ void seg_issue_tile(float* dstbase, int tid, int s0, int n, int tb)
{
#pragma unroll
    for (int j = 0; j < 6; j++) {
        int idx = tid + j * 256;
        if (idx < TROW * (TS / 2)) {
            int c = idx >> 3;                 // channel 0..188
            int pe = idx & 7;                 // pair index within tile
            int eoff = tb + pe * 2;
            int rem = n - eoff;
            int sz = (rem >= 2) ? 8 : ((rem == 1) ? 4 : 0);
            const float* src;
            if (sz == 0) {
                src = g_radial;               // safe dummy, zero-filled anyway
            } else {
                src = ((c < 120) ? (g_radial + (size_t)c * NE)
                                 : (g_gv + (size_t)(c - 120) * NE)) + s0 + eoff;
            }
            unsigned d = (unsigned)__cvta_generic_to_shared(dstbase + c * TSTRIDE + pe * 2);
            asm volatile("cp.async.ca.shared.global [%0], [%1], 8, %2;\n"
                         :: "r"(d), "l"(src), "r"(sz));
        }
    }
    asm volatile("cp.async.commit_group;\n");
}

// ---------------- kernel: per-atom segment sum, cp.async double-buffered mini-GEMM ----------------
// warp = group of 3 radial rows (broadcast), lane = chunk of 2-3 same-zone k's.
__global__ __launch_bounds__(256) void seg_kernel()
{
    int a = blockIdx.x;
    int tid = threadIdx.x;
    int s0raw = g_segstart[a];
    int s1    = g_segstart[a + 1];
    int ghost = s0raw & 1;          // 1 if we must pad one leading edge for alignment
    int s0    = s0raw - ghost;      // even base -> 8B-aligned cp.async sources
    int n     = s1 - s0;            // includes ghost edge (zeroed below)

    __shared__ __align__(16) float sbuf[2 * TILEW];
    __shared__ float sgi[NPAIR];
    __shared__ float slam[KTOT];
    if (tid == 0) {
        int k = 0;
        for (int z = 1; z <= 4; z++)
            for (int nn = 0; nn <= z; nn++) {
                int cnt = (nn + 1) * (nn + 2) / 2;
                float l = (nn & 1) ? -1.f : 1.f;
                for (int i = 0; i < cnt; i++) slam[k++] = l;
            }
    }

    // 3x3 register tile: rows rg*3+{0,1,2}, cols klo..klo+nk-1
    int rg = tid >> 5;
    int ck = tid & 31;
    int klo = c_klo[ck];
    int nk  = c_nk[ck];
    int z   = (klo < 4) ? 0 : (klo < 14) ? 1 : (klo < 34) ? 2 : 3;
    int rb0 = ((rg * 3 + 0) * NCOMP + z + 1) * TSTRIDE;
    int rb1 = ((rg * 3 + 1) * NCOMP + z + 1) * TSTRIDE;
    int rb2 = ((rg * 3 + 2) * NCOMP + z + 1) * TSTRIDE;
    int gb0 = (120 + klo) * TSTRIDE;
    int gb1 = (120 + klo + ((nk > 1) ? 1 : 0)) * TSTRIDE;
    int gb2 = (120 + klo + ((nk > 2) ? 2 : 0)) * TSTRIDE;
    u64 acc[9];
#pragma unroll
    for (int i = 0; i < 9; i++) acc[i] = 0;
    float f0 = 0.f;

    int ntiles = (n + TS - 1) / TS;

    if (ntiles > 0) seg_issue_tile(sbuf, tid, s0, n, 0);

    for (int t = 0; t < ntiles; t++) {
        if (t + 1 < ntiles) {
            seg_issue_tile(sbuf + ((t + 1) & 1) * TILEW, tid, s0, n, (t + 1) * TS);
            asm volatile("cp.async.wait_group 1;\n");
        } else {
            asm volatile("cp.async.wait_group 0;\n");
        }
        __syncthreads();
        float* B = sbuf + (t & 1) * TILEW;
        if (t == 0 && ghost) {
            // zero the ghost (alignment-pad) edge column so it contributes nothing
            for (int idx = tid; idx < TROW; idx += 256) B[idx * TSTRIDE] = 0.f;
            __syncthreads();
        }
#pragma unroll
        for (int e = 0; e < TS; e += 2) {
            u64 r0 = *(const u64*)(B + rb0 + e);
            u64 r1 = *(const u64*)(B + rb1 + e);
            u64 r2 = *(const u64*)(B + rb2 + e);
            u64 g0 = *(const u64*)(B + gb0 + e);
            u64 g1 = *(const u64*)(B + gb1 + e);
            u64 g2 = *(const u64*)(B + gb2 + e);
            acc[0] = ffma2(r0, g0, acc[0]);
            acc[1] = ffma2(r0, g1, acc[1]);
            acc[2] = ffma2(r0, g2, acc[2]);
            acc[3] = ffma2(r1, g0, acc[3]);
            acc[4] = ffma2(r1, g1, acc[4]);
            acc[5] = ffma2(r1, g2, acc[5]);
            acc[6] = ffma2(r2, g0, acc[6]);
            acc[7] = ffma2(r2, g1, acc[7]);
            acc[8] = ffma2(r2, g2, acc[8]);
        }
        if (tid < 24) {
#pragma unroll
            for (int e = 0; e < TS; e++) f0 += B[tid * (NCOMP * TSTRIDE) + e];
        }
        __syncthreads();
    }

    // write 3 x nk tile into sgi
#pragma unroll
    for (int i = 0; i < 3; i++) {
#pragma unroll
        for (int j = 0; j < 3; j++) {
            if (j < nk) {
                float x, y; upk2(acc[i * 3 + j], x, y);
                sgi[(rg * 3 + i) * KTOT + klo + j] = x + y;
            }
        }
    }
    __syncthreads();

    const float norm[4] = {1.f, 0.5f, 0.25f, 0.125f};
    const int koff[5] = {0, 4, 14, 34, KTOT};
    if (tid < 24) g_feat[a * FEAT + tid] = f0;
    if (tid < 192) {
        int iz = tid / 48;
        int j = tid % 48;
        int lamf = j / 24;
        int rr = j % 24;
        float s = 0.f;
        for (int k = koff[iz]; k < koff[iz + 1]; k++) {
            float v = sgi[rr * KTOT + k];
            float tt = v * v;
            s += lamf ? tt * slam[k] : tt;
        }
        g_feat[a * FEAT + 24 + iz * 48 + lamf * 24 + rr] = s * norm[iz];
    }
}

// ---------------- kernel: hist + parallel scan + scatter in one CTA ----------------
__global__ __launch_bounds__(256) void bucket_kernel(const int* __restrict__ sp)
{
    __shared__ int c[NELEM];
    __shared__ int sc[NELEM];
    __shared__ int off[NELEM];
    int tid = threadIdx.x;
    if (tid < NELEM) c[tid] = 0;
    __syncthreads();
    for (int a = tid; a < NATOMS; a += 256) atomicAdd(&c[sp[a]], 1);
    __syncthreads();
    if (tid < NELEM) sc[tid] = c[tid];
    __syncthreads();
#pragma unroll
    for (int d = 1; d < 128; d <<= 1) {
        int v = (tid < NELEM && tid >= d) ? sc[tid - d] : 0;
        __syncthreads();
        if (tid < NELEM) sc[tid] += v;
        __syncthreads();
    }
    if (tid < NELEM) {
        int o = sc[tid] - c[tid];
        off[tid] = o; g_off[tid] = o; g_cnt[tid] = c[tid];
    }
    __syncthreads();
    for (int a = tid; a < NATOMS; a += 256) {
        int p = atomicAdd(&off[sp[a]], 1);
        g_order[p] = a;
    }
}

// ---------------- kernel: species embedding + fold Wa1 (fused) ----------------
__global__ __launch_bounds__(256) void bprep_kernel(
    const float* __restrict__ Ws1, const float* __restrict__ bs1,
    const float* __restrict__ Ws2, const float* __restrict__ bs2,
    const float* __restrict__ Wa1)
{
    int f = blockIdx.x;            // 0..215
    int tid = threadIdx.x;         // output o
    __shared__ __align__(16) float sW[16 * 256];
    __shared__ float semb[NELEM * EMBD];
    for (int i = tid; i < 16 * 256; i += 256) sW[i] = Wa1[(size_t)f * 16 * 256 + i];
    if (tid < NELEM) {
        float h[32];
#pragma unroll
        for (int j = 0; j < 32; j++) h[j] = silu_acc(Ws1[tid * 32 + j] + bs1[j]);
#pragma unroll
        for (int m = 0; m < EMBD; m++) {
            float a = bs2[m];
#pragma unroll
            for (int j = 0; j < 32; j++) a += h[j] * Ws2[j * EMBD + m];
            semb[tid * EMBD + m] = a;
        }
    }
    __syncthreads();
    for (int s = 0; s < NELEM; s++) {
        float acc = 0.f;
#pragma unroll
        for (int m = 0; m < 16; m++) acc += semb[s * EMBD + m] * sW[m * 256 + tid];
        g_B[((size_t)s * FEAT + f) * H1N + tid] = acc;
    }
}

// ---------------- kernel: species-bucketed atom MLP (8 atoms/CTA) ----------------
__global__ __launch_bounds__(256) void atomgemm_kernel(
    const float* __restrict__ ba1,
    const float* __restrict__ Wa2, const float* __restrict__ ba2,
    const float* __restrict__ Wa3, const float* __restrict__ ba3)
{
    int s = blockIdx.y, ch = blockIdx.x;
    int cnt = g_cnt[s];
    int a0 = ch * 8;
    if (a0 >= cnt) return;
    int nA = min(8, cnt - a0);
    int base = g_off[s] + a0;
    int tid = threadIdx.x;

    __shared__ float sfeat[8][FEAT];
    __shared__ int aid[8];
    __shared__ float sh1[8][H1N];
    __shared__ float sh2[8][H2N];

    if (tid < 8) aid[tid] = (tid < nA) ? g_order[base + tid] : -1;
    __syncthreads();
    for (int i = tid; i < 8 * FEAT; i += 256) {
        int aa = i / FEAT, f = i - aa * FEAT;
        sfeat[aa][f] = (aa < nA) ? g_feat[aid[aa] * FEAT + f] : 0.f;
    }
    __syncthreads();

    const float* Bp = g_B + (size_t)s * FEAT * H1N;
    float acc[8];
    float b1 = ba1[tid];
#pragma unroll
    for (int i = 0; i < 8; i++) acc[i] = b1;
#pragma unroll 8
    for (int f = 0; f < FEAT; f++) {
        float w = Bp[(size_t)f * H1N + tid];
#pragma unroll
        for (int i = 0; i < 8; i++) acc[i] += sfeat[i][f] * w;
    }
#pragma unroll
    for (int i = 0; i < 8; i++) sh1[i][tid] = silu_acc(acc[i]);
    __syncthreads();

    // layer2: 8 atoms x 128 outputs = 1024 tasks over 256 threads
#pragma unroll
    for (int t = 0; t < 4; t++) {
        int task = tid + t * 256;
        int aa = task >> 7, o = task & 127;
        float a2 = ba2[o];
#pragma unroll 8
        for (int j = 0; j < H1N; j++) a2 += sh1[aa][j] * Wa2[j * H2N + o];
        sh2[aa][o] = silu_acc(a2);
    }
    __syncthreads();

    // layer3: warp w reduces atom w
    int w = tid >> 5, l = tid & 31;
    float p = sh2[w][l] * Wa3[l] + sh2[w][l + 32] * Wa3[l + 32]
            + sh2[w][l + 64] * Wa3[l + 64] + sh2[w][l + 96] * Wa3[l + 96];
#pragma unroll
    for (int off = 16; off; off >>= 1) p += __shfl_down_sync(0xffffffffu, p, off);
    if (l == 0 && w < nA) g_energy[aid[w]] = p + ba3[0];
}

// ---------------- final deterministic reduction ----------------
__global__ __launch_bounds__(1024) void reduce_kernel(float* __restrict__ out)
{
    __shared__ float sred[32];
    int tid = threadIdx.x;
    float v = g_energy[tid] + g_energy[tid + 1024];
#pragma unroll
    for (int off = 16; off; off >>= 1) v += __shfl_down_sync(0xffffffffu, v, off);
    if ((tid & 31) == 0) sred[tid >> 5] = v;
    __syncthreads();
    if (tid < 32) {
        float t = sred[tid];
#pragma unroll
        for (int off = 16; off; off >>= 1) t += __shfl_down_sync(0xffffffffu, t, off);
        if (tid == 0) out[0] = t;
    }
}

// ---------------- launch ----------------
extern "C" void kernel_launch(void* const* d_in, const int* in_sizes, int n_in,
                              void* d_out, int out_size)
{
    const float* rij = (const float*)d_in[0];
    const float* Wr1 = (const float*)d_in[1];
    const float* br1 = (const float*)d_in[2];
    const float* Wr2 = (const float*)d_in[3];
    const float* br2 = (const float*)d_in[4];
    const float* Ws1 = (const float*)d_in[5];
    const float* bs1 = (const float*)d_in[6];
    const float* Ws2 = (const float*)d_in[7];
    const float* bs2 = (const float*)d_in[8];
    const float* Wa1 = (const float*)d_in[9];
    const float* ba1 = (const float*)d_in[10];
    const float* Wa2 = (const float*)d_in[11];
    const float* ba2 = (const float*)d_in[12];
    const float* Wa3 = (const float*)d_in[13];
    const float* ba3 = (const float*)d_in[14];
    const int* first_atom_idx = (const int*)d_in[15];
    const int* species_idx = (const int*)d_in[16];
    float* out = (float*)d_out;

    // order chosen so ncu lands on seg_kernel (4th launch)
    segstart_kernel<<<NE / 256, 256>>>(first_atom_idx);
    bucket_kernel<<<1, 256>>>(species_idx);
    edge_kernel<<<NE / 256, 128>>>(rij, Wr1, br1, Wr2, br2);
    seg_kernel<<<NATOMS, 256>>>();
    bprep_kernel<<<FEAT, 256>>>(Ws1, bs1, Ws2, bs2, Wa1);
    atomgemm_kernel<<<dim3(16, NELEM), 256>>>(ba1, Wa2, ba2, Wa3, ba3);
    reduce_kernel<<<1, 1024>>>(out);
}

// round 15
// speedup vs baseline: 1.4070x; 1.4070x over previous
#include <cuda_runtime.h>
#include <cuda_bf16.h>
#include <math.h>

#define NE      65536
#define NATOMS  2048
#define NRAD    24
#define NCOMP   5
#define KTOT    69
#define NPAIR   (NRAD*KTOT)
#define FEAT    216
#define EMBD    16
#define NELEM   94
#define H1N     256
#define H2N     128
#define TS      8
#define TROW    189
#define TSTRIDE 10
#define TILEW   (TROW*TSTRIDE)

typedef unsigned long long u64;

__device__ float g_radial[120 * NE];
__device__ float g_gv[KTOT * NE];
__device__ float g_feat[NATOMS * FEAT];
__device__ float g_B[(size_t)NELEM * FEAT * H1N];
__device__ int   g_segstart[NATOMS + 1];
__device__ int   g_cnt[NELEM];
__device__ int   g_off[NELEM];
__device__ int   g_order[NATOMS];
__device__ float g_energy[NATOMS];

__constant__ int c_klo[32] = {0,2,4,6,8,10,12,14,17,20,23,26,29,32,
                              34,36,38,40,42,44,46,48,50,52,54,56,58,60,62,64,66,68};
__constant__ int c_nk[32]  = {2,2,2,2,2,2,2,3,3,3,3,3,3,2,
                              2,2,2,2,2,2,2,2,2,2,2,2,2,2,2,2,2,1};

__device__ __forceinline__ u64 pk2(float lo, float hi) {
    u64 r; asm("mov.b64 %0,{%1,%2};" : "=l"(r) : "f"(lo), "f"(hi)); return r;
}
__device__ __forceinline__ void upk2(u64 v, float& lo, float& hi) {
    asm("mov.b64 {%0,%1},%2;" : "=f"(lo), "=f"(hi) : "l"(v));
}
__device__ __forceinline__ u64 ffma2(u64 a, u64 b, u64 c) {
    u64 d; asm("fma.rn.f32x2 %0,%1,%2,%3;" : "=l"(d) : "l"(a), "l"(b), "l"(c)); return d;
}
__device__ __forceinline__ float silu_fast(float x) {
    return __fdividef(x, 1.f + __expf(-x));
}
__device__ __forceinline__ float silu_acc(float x) {
    return x / (1.f + expf(-x));
}

// ---------------- setup: segstart (blocks 0..255) + species bucketing (block 256) ----------------
__global__ __launch_bounds__(256) void setup_kernel(const int* __restrict__ seg,
                                                    const int* __restrict__ sp)
{
    int tid = threadIdx.x;
    if (blockIdx.x < 256) {
        int e = blockIdx.x * 256 + tid;
        int cur = seg[e];
        int prev = (e == 0) ? -1 : seg[e - 1];
        for (int a = prev + 1; a <= cur; a++) g_segstart[a] = e;
        if (e == NE - 1)
            for (int a = cur + 1; a <= NATOMS; a++) g_segstart[a] = NE;
        return;
    }
    __shared__ int c[NELEM];
    __shared__ int sc[NELEM];
    __shared__ int off[NELEM];
    if (tid < NELEM) c[tid] = 0;
    __syncthreads();
    for (int a = tid; a < NATOMS; a += 256) atomicAdd(&c[sp[a]], 1);
    __syncthreads();
    if (tid < NELEM) sc[tid] = c[tid];
    __syncthreads();
#pragma unroll
    for (int d = 1; d < 128; d <<= 1) {
        int v = (tid < NELEM && tid >= d) ? sc[tid - d] : 0;
        __syncthreads();
        if (tid < NELEM) sc[tid] += v;
        __syncthreads();
    }
    if (tid < NELEM) {
        int o = sc[tid] - c[tid];
        off[tid] = o; g_off[tid] = o; g_cnt[tid] = c[tid];
    }
    __syncthreads();
    for (int a = tid; a < NATOMS; a += 256) {
        int p = atomicAdd(&off[sp[a]], 1);
        g_order[p] = a;
    }
}

// ---------------- species embedding + fold Wa1 (fused) ----------------
__global__ __launch_bounds__(256) void bprep_kernel(
    const float* __restrict__ Ws1, const float* __restrict__ bs1,
    const float* __restrict__ Ws2, const float* __restrict__ bs2,
    const float* __restrict__ Wa1)
{
    int f = blockIdx.x;
    int tid = threadIdx.x;
    __shared__ __align__(16) float sW[16 * 256];
    __shared__ float semb[NELEM * EMBD];
    for (int i = tid; i < 16 * 256; i += 256) sW[i] = Wa1[(size_t)f * 16 * 256 + i];
    if (tid < NELEM) {
        float h[32];
#pragma unroll
        for (int j = 0; j < 32; j++) h[j] = silu_acc(Ws1[tid * 32 + j] + bs1[j]);
#pragma unroll
        for (int m = 0; m < EMBD; m++) {
            float a = bs2[m];
#pragma unroll
            for (int j = 0; j < 32; j++) a += h[j] * Ws2[j * EMBD + m];
            semb[tid * EMBD + m] = a;
        }
    }
    __syncthreads();
    for (int s = 0; s < NELEM; s++) {
        float acc = 0.f;
#pragma unroll
        for (int m = 0; m < 16; m++) acc += semb[s * EMBD + m] * sW[m * 256 + tid];
        g_B[((size_t)s * FEAT + f) * H1N + tid] = acc;
    }
}

// ---------------- per-edge radial MLP + angular factors (2 edges/thread) ----------------
__global__ __launch_bounds__(128) void edge_kernel(
    const float* __restrict__ rij,
    const float* __restrict__ Wr1, const float* __restrict__ br1,
    const float* __restrict__ Wr2, const float* __restrict__ br2)
{
    __shared__ __align__(16) float sW1[24 * 64];
    __shared__ __align__(16) float sW2[64 * 120];
    __shared__ __align__(16) float sb1[64];
    __shared__ __align__(16) float sb2[120];

    int tid = threadIdx.x;
    for (int i = tid; i < 24 * 64; i += 128)  sW1[i] = Wr1[i];
    for (int i = tid; i < 64 * 120; i += 128) sW2[i] = Wr2[i];
    if (tid < 64)  sb1[tid] = br1[tid];
    if (tid < 120) sb2[tid] = br2[tid];
    __syncthreads();

    int e0 = blockIdx.x * 256 + tid;
    int e1 = e0 + 128;

    float ux0, uy0, uz0, ux1, uy1, uz1;
    float basis0[24], basis1[24];
    {
        float x = rij[e0*3+0], y = rij[e0*3+1], z = rij[e0*3+2];
        float r = sqrtf(x*x + y*y + z*z);
        float inv = 1.f / r;
        ux0 = x*inv + 1e-12f; uy0 = y*inv + 1e-12f; uz0 = z*inv + 1e-12f;
        float fc = 0.5f * (__cosf(3.14159265358979323846f * fminf(r, 6.f) * (1.f/6.f)) + 1.f);
#pragma unroll
        for (int k = 0; k < 24; k++) {
            float d = r - (6.f/23.f)*(float)k;
            basis0[k] = __expf(-d*d*8.f) * fc;
        }
    }
    {
        float x = rij[e1*3+0], y = rij[e1*3+1], z = rij[e1*3+2];
        float r = sqrtf(x*x + y*y + z*z);
        float inv = 1.f / r;
        ux1 = x*inv + 1e-12f; uy1 = y*inv + 1e-12f; uz1 = z*inv + 1e-12f;
        float fc = 0.5f * (__cosf(3.14159265358979323846f * fminf(r, 6.f) * (1.f/6.f)) + 1.f);
#pragma unroll
        for (int k = 0; k < 24; k++) {
            float d = r - (6.f/23.f)*(float)k;
            basis1[k] = __expf(-d*d*8.f) * fc;
        }
    }

    float h0[64], h1[64];
#pragma unroll
    for (int c = 0; c < 2; c++) {
        u64 a0[16], a1[16];
        {
            const ulonglong2* bp = (const ulonglong2*)(sb1 + c * 32);
#pragma unroll
            for (int t = 0; t < 8; t++) {
                ulonglong2 b = bp[t];
                a0[2*t] = b.x; a0[2*t+1] = b.y;
                a1[2*t] = b.x; a1[2*t+1] = b.y;
            }
        }
#pragma unroll
        for (int k = 0; k < 24; k++) {
            u64 p0 = pk2(basis0[k], basis0[k]);
            u64 p1 = pk2(basis1[k], basis1[k]);
            const ulonglong2* w = (const ulonglong2*)(sW1 + k * 64 + c * 32);
#pragma unroll
            for (int t = 0; t < 8; t++) {
                ulonglong2 ww = w[t];
                a0[2*t]   = ffma2(p0, ww.x, a0[2*t]);
                a0[2*t+1] = ffma2(p0, ww.y, a0[2*t+1]);
                a1[2*t]   = ffma2(p1, ww.x, a1[2*t]);
                a1[2*t+1] = ffma2(p1, ww.y, a1[2*t+1]);
            }
        }
#pragma unroll
        for (int t = 0; t < 16; t++) {
            float x, y;
            upk2(a0[t], x, y);
            h0[c*32 + 2*t] = silu_fast(x); h0[c*32 + 2*t + 1] = silu_fast(y);
            upk2(a1[t], x, y);
            h1[c*32 + 2*t] = silu_fast(x); h1[c*32 + 2*t + 1] = silu_fast(y);
        }
    }

#pragma unroll 1
    for (int c = 0; c < 6; c++) {
        u64 a0[10], a1[10];
        {
            const ulonglong2* bp = (const ulonglong2*)(sb2 + c * 20);
#pragma unroll
            for (int t = 0; t < 5; t++) {
                ulonglong2 b = bp[t];
                a0[2*t] = b.x; a0[2*t+1] = b.y;
                a1[2*t] = b.x; a1[2*t+1] = b.y;
            }
        }
#pragma unroll 16
        for (int j = 0; j < 64; j++) {
            u64 p0 = pk2(h0[j], h0[j]);
            u64 p1 = pk2(h1[j], h1[j]);
            const ulonglong2* w = (const ulonglong2*)(sW2 + j * 120 + c * 20);
#pragma unroll
            for (int t = 0; t < 5; t++) {
                ulonglong2 ww = w[t];
                a0[2*t]   = ffma2(p0, ww.x, a0[2*t]);
                a0[2*t+1] = ffma2(p0, ww.y, a0[2*t+1]);
                a1[2*t]   = ffma2(p1, ww.x, a1[2*t]);
                a1[2*t+1] = ffma2(p1, ww.y, a1[2*t+1]);
            }
        }
#pragma unroll
        for (int t = 0; t < 10; t++) {
            float x, y;
            int o = c * 20 + 2 * t;
            upk2(a0[t], x, y);
            g_radial[(size_t)o * NE + e0]       = silu_fast(x);
            g_radial[(size_t)(o + 1) * NE + e0] = silu_fast(y);
            upk2(a1[t], x, y);
            g_radial[(size_t)o * NE + e1]       = silu_fast(x);
            g_radial[(size_t)(o + 1) * NE + e1] = silu_fast(y);
        }
    }

    const float FACT[5] = {1.f, 1.f, 2.f, 6.f, 24.f};
#pragma unroll
    for (int pass = 0; pass < 2; pass++) {
        float ux = pass ? ux1 : ux0, uy = pass ? uy1 : uy0, uz = pass ? uz1 : uz0;
        int e = pass ? e1 : e0;
        float px[5], py[5], pz[5];
        px[0] = 1.f; py[0] = 1.f; pz[0] = 1.f;
#pragma unroll
        for (int n = 1; n < 5; n++) { px[n] = px[n-1]*ux; py[n] = py[n-1]*uy; pz[n] = pz[n-1]*uz; }
        int k = 0;
#pragma unroll
        for (int z5 = 1; z5 <= 4; z5++) {
#pragma unroll
            for (int n = 0; n <= z5; n++) {
#pragma unroll
                for (int a = 0; a <= n; a++) {
#pragma unroll
                    for (int b = 0; b <= n - a; b++) {
                        int cc = n - a - b;
                        float fn = FACT[z5] / (FACT[z5 - n] * FACT[a] * FACT[b] * FACT[cc]);
                        g_gv[(size_t)k * NE + e] = fn * px[a] * py[b] * pz[cc];
                        k++;
                    }
                }
            }
        }
    }
}

// ---------------- per-atom segment sum, register-tiled mini-GEMM ----------------
__global__ __launch_bounds__(256) void seg_kernel()
{
    int a = blockIdx.x;
    int tid = threadIdx.x;
    int s0 = g_segstart[a];
    int n  = g_segstart[a + 1] - s0;

    __shared__ __align__(16) float sbuf[2 * TILEW];
    __shared__ float sgi[NPAIR];
    __shared__ float slam[KTOT];
    if (tid == 0) {
        int k = 0;
        for (int z = 1; z <= 4; z++)
            for (int nn = 0; nn <= z; nn++) {
                int cnt = (nn + 1) * (nn + 2) / 2;
                float l = (nn & 1) ? -1.f : 1.f;
                for (int i = 0; i < cnt; i++) slam[k++] = l;
            }
    }

    int rg = tid >> 5;
    int ck = tid & 31;
    int klo = c_klo[ck];
    int nk  = c_nk[ck];
    int z   = (klo < 4) ? 0 : (klo < 14) ? 1 : (klo < 34) ? 2 : 3;
    int rb0 = ((rg * 3 + 0) * NCOMP + z + 1) * TSTRIDE;
    int rb1 = ((rg * 3 + 1) * NCOMP + z + 1) * TSTRIDE;
    int rb2 = ((rg * 3 + 2) * NCOMP + z + 1) * TSTRIDE;
    int gb0 = (120 + klo) * TSTRIDE;
    int gb1 = (120 + klo + ((nk > 1) ? 1 : 0)) * TSTRIDE;
    int gb2 = (120 + klo + ((nk > 2) ? 2 : 0)) * TSTRIDE;
    u64 acc[9];
#pragma unroll
    for (int i = 0; i < 9; i++) acc[i] = 0;
    float f0 = 0.f;

    const float* src[6]; int dst[6], eo[6]; bool ok[6];
#pragma unroll
    for (int j = 0; j < 6; j++) {
        int idx = tid + j * 256;
        ok[j] = (idx < TROW * TS);
        if (ok[j]) {
            int c = idx >> 3; eo[j] = idx & 7;
            src[j] = ((c < 120) ? (g_radial + (size_t)c * NE)
                                : (g_gv + (size_t)(c - 120) * NE)) + eo[j];
            dst[j] = c * TSTRIDE + eo[j];
        } else { src[j] = g_radial; dst[j] = 0; eo[j] = 0; }
    }
    __syncthreads();

    int ntiles = (n + TS - 1) / TS;
    float pf[6];
#pragma unroll
    for (int j = 0; j < 6; j++)
        pf[j] = (ok[j] && eo[j] < n) ? src[j][s0] : 0.f;

    for (int t = 0; t < ntiles; t++) {
        float* B = sbuf + (t & 1) * TILEW;
#pragma unroll
        for (int j = 0; j < 6; j++)
            if (ok[j]) B[dst[j]] = pf[j];
        int nb = (t + 1) * TS;
#pragma unroll
        for (int j = 0; j < 6; j++)
            pf[j] = (ok[j] && nb + eo[j] < n) ? src[j][s0 + nb] : 0.f;
        __syncthreads();
#pragma unroll
        for (int e = 0; e < TS; e += 2) {
            u64 r0 = *(const u64*)(B + rb0 + e);
            u64 r1 = *(const u64*)(B + rb1 + e);
            u64 r2 = *(const u64*)(B + rb2 + e);
            u64 g0 = *(const u64*)(B + gb0 + e);
            u64 g1 = *(const u64*)(B + gb1 + e);
            u64 g2 = *(const u64*)(B + gb2 + e);
            acc[0] = ffma2(r0, g0, acc[0]);
            acc[1] = ffma2(r0, g1, acc[1]);
            acc[2] = ffma2(r0, g2, acc[2]);
            acc[3] = ffma2(r1, g0, acc[3]);
            acc[4] = ffma2(r1, g1, acc[4]);
            acc[5] = ffma2(r1, g2, acc[5]);
            acc[6] = ffma2(r2, g0, acc[6]);
            acc[7] = ffma2(r2, g1, acc[7]);
            acc[8] = ffma2(r2, g2, acc[8]);
        }
        if (tid < 24) {
#pragma unroll
            for (int e = 0; e < TS; e++) f0 += B[tid * (NCOMP * TSTRIDE) + e];
        }
        __syncthreads();
    }

#pragma unroll
    for (int i = 0; i < 3; i++) {
#pragma unroll
        for (int j = 0; j < 3; j++) {
            if (j < nk) {
                float x, y; upk2(acc[i * 3 + j], x, y);
                sgi[(rg * 3 + i) * KTOT + klo + j] = x + y;
            }
        }
    }
    __syncthreads();

    const float norm[4] = {1.f, 0.5f, 0.25f, 0.125f};
    const int koff[5] = {0, 4, 14, 34, KTOT};
    if (tid < 24) g_feat[a * FEAT + tid] = f0;
    if (tid < 192) {
        int iz = tid / 48;
        int j = tid % 48;
        int lamf = j / 24;
        int rr = j % 24;
        float s = 0.f;
        for (int k = koff[iz]; k < koff[iz + 1]; k++) {
            float v = sgi[rr * KTOT + k];
            float tt = v * v;
            s += lamf ? tt * slam[k] : tt;
        }
        g_feat[a * FEAT + 24 + iz * 48 + lamf * 24 + rr] = s * norm[iz];
    }
}

// ---------------- species-bucketed atom MLP (8 atoms/CTA) ----------------
__global__ __launch_bounds__(256) void atomgemm_kernel(
    const float* __restrict__ ba1,
    const float* __restrict__ Wa2, const float* __restrict__ ba2,
    const float* __restrict__ Wa3, const float* __restrict__ ba3)
{
    int s = blockIdx.y, ch = blockIdx.x;
    int cnt = g_cnt[s];
    int a0 = ch * 8;
    if (a0 >= cnt) return;
    int nA = min(8, cnt - a0);
    int base = g_off[s] + a0;
    int tid = threadIdx.x;

    __shared__ float sfeat[8][FEAT];
    __shared__ int aid[8];
    __shared__ float sh1[8][H1N];
    __shared__ float sh2[8][H2N];

    if (tid < 8) aid[tid] = (tid < nA) ? g_order[base + tid] : -1;
    __syncthreads();
    for (int i = tid; i < 8 * FEAT; i += 256) {
        int aa = i / FEAT, f = i - aa * FEAT;
        sfeat[aa][f] = (aa < nA) ? g_feat[aid[aa] * FEAT + f] : 0.f;
    }
    __syncthreads();

    const float* Bp = g_B + (size_t)s * FEAT * H1N;
    float acc[8];
    float b1 = ba1[tid];
#pragma unroll
    for (int i = 0; i < 8; i++) acc[i] = b1;
#pragma unroll 8
    for (int f = 0; f < FEAT; f++) {
        float w = Bp[(size_t)f * H1N + tid];
#pragma unroll
        for (int i = 0; i < 8; i++) acc[i] += sfeat[i][f] * w;
    }
#pragma unroll
    for (int i = 0; i < 8; i++) sh1[i][tid] = silu_acc(acc[i]);
    __syncthreads();

#pragma unroll
    for (int t = 0; t < 4; t++) {
        int task = tid + t * 256;
        int aa = task >> 7, o = task & 127;
        float a2 = ba2[o];
#pragma unroll 8
        for (int j = 0; j < H1N; j++) a2 += sh1[aa][j] * Wa2[j * H2N + o];
        sh2[aa][o] = silu_acc(a2);
    }
    __syncthreads();

    int w = tid >> 5, l = tid & 31;
    float p = sh2[w][l] * Wa3[l] + sh2[w][l + 32] * Wa3[l + 32]
            + sh2[w][l + 64] * Wa3[l + 64] + sh2[w][l + 96] * Wa3[l + 96];
#pragma unroll
    for (int off = 16; off; off >>= 1) p += __shfl_down_sync(0xffffffffu, p, off);
    if (l == 0 && w < nA) g_energy[aid[w]] = p + ba3[0];
}

// ---------------- final deterministic reduction ----------------
__global__ __launch_bounds__(1024) void reduce_kernel(float* __restrict__ out)
{
    __shared__ float sred[32];
    int tid = threadIdx.x;
    float v = g_energy[tid] + g_energy[tid + 1024];
#pragma unroll
    for (int off = 16; off; off >>= 1) v += __shfl_down_sync(0xffffffffu, v, off);
    if ((tid & 31) == 0) sred[tid >> 5] = v;
    __syncthreads();
    if (tid < 32) {
        float t = sred[tid];
#pragma unroll
        for (int off = 16; off; off >>= 1) t += __shfl_down_sync(0xffffffffu, t, off);
        if (tid == 0) out[0] = t;
    }
}

// ---------------- launch ----------------
extern "C" void kernel_launch(void* const* d_in, const int* in_sizes, int n_in,
                              void* d_out, int out_size)
{
    const float* rij = (const float*)d_in[0];
    const float* Wr1 = (const float*)d_in[1];
    const float* br1 = (const float*)d_in[2];
    const float* Wr2 = (const float*)d_in[3];
    const float* br2 = (const float*)d_in[4];
    const float* Ws1 = (const float*)d_in[5];
    const float* bs1 = (const float*)d_in[6];
    const float* Ws2 = (const float*)d_in[7];
    const float* bs2 = (const float*)d_in[8];
    const float* Wa1 = (const float*)d_in[9];
    const float* ba1 = (const float*)d_in[10];
    const float* Wa2 = (const float*)d_in[11];
    const float* ba2 = (const float*)d_in[12];
    const float* Wa3 = (const float*)d_in[13];
    const float* ba3 = (const float*)d_in[14];
    const int* first_atom_idx = (const int*)d_in[15];
    const int* species_idx = (const int*)d_in[16];
    float* out = (float*)d_out;

    // order: setup(1), bprep(2), seg? needs edge... edge(3), edge is 4th with -s skip
    setup_kernel<<<257, 256>>>(first_atom_idx, species_idx);
    bprep_kernel<<<FEAT, 256>>>(Ws1, bs1, Ws2, bs2, Wa1);
    edge_kernel<<<NE / 256, 128>>>(rij, Wr1, br1, Wr2, br2);
    seg_kernel<<<NATOMS, 256>>>();
    atomgemm_kernel<<<dim3(16, NELEM), 256>>>(ba1, Wa2, ba2, Wa3, ba3);
    reduce_kernel<<<1, 1024>>>(out);
}